// round 1
// baseline (speedup 1.0000x reference)
#include <cuda_runtime.h>
#include <math.h>

// TransitionGNN fused kernel.
// Shapes: B=8192, K=10, D=64, H=128, A=16, E=90, F=208.
// One block handles (node i, 64-row batch tile):
//   for each j != i: msg = tanh([s_i|s_j] @ W_edge[e(i,j)] + b_edge); agg += msg
//   out = tanh([s_i|act|agg] @ W_node[i] + b_node[i])
//
// Edge index for ordered pair (i,j): e = i*9 + (j < i ? j : j-1)   (lexicographic, skip diag)

#define KNODES 10
#define DDIM   64
#define HDIM   128
#define ADIM   16
#define FDIM   208   // D + A + H
#define TB     64    // batch rows per block
#define PAD    68    // smem row stride (floats), multiple of 4 for float4 alignment

__device__ __forceinline__ void gemm_half(const float* __restrict__ aT,   // [64][PAD] (k-major, row=batch)
                                          const float* __restrict__ wbase,// [64][128]
                                          float acc[4][8], int ty, int tx)
{
    #pragma unroll 8
    for (int k = 0; k < 64; ++k) {
        float4 a4 = *(const float4*)&aT[k * PAD + ty * 4];
        float4 w0 = *(const float4*)&wbase[k * 128 + tx * 8];
        float4 w1 = *(const float4*)&wbase[k * 128 + tx * 8 + 4];
        float av[4] = {a4.x, a4.y, a4.z, a4.w};
        float wv[8] = {w0.x, w0.y, w0.z, w0.w, w1.x, w1.y, w1.z, w1.w};
        #pragma unroll
        for (int rr = 0; rr < 4; ++rr)
            #pragma unroll
            for (int cc = 0; cc < 8; ++cc)
                acc[rr][cc] = fmaf(av[rr], wv[cc], acc[rr][cc]);
    }
}

extern "C" __global__ void __launch_bounds__(256, 1)
gnn_fused_kernel(const float* __restrict__ states,     // [B,K,D]
                 const float* __restrict__ action,     // [B,K,A]
                 const float* __restrict__ W_edge,     // [E,2D,H] = [90,128,128]
                 const float* __restrict__ b_edge,     // [E,H]
                 const float* __restrict__ W_node,     // [K,F,D] = [10,208,64]
                 const float* __restrict__ b_node,     // [K,D]
                 float* __restrict__ out)              // [B,K,D]
{
    extern __shared__ float sm[];
    float* siT  = sm;                    // [64][PAD]  states of node i, transposed (d, row)
    float* sjT  = siT  + 64  * PAD;      // [64][PAD]  states of node j
    float* aggT = sjT  + 64  * PAD;      // [128][PAD] aggregated messages, transposed (h, row)
    float* actT = aggT + 128 * PAD;      // [16][PAD]  actions, transposed (a, row)
    float* w_s  = actT + 16  * PAD;      // [128][128] edge W tile; reused as [208][64] node W

    const int i   = blockIdx.y;          // node index
    const int b0  = blockIdx.x * TB;     // batch tile origin
    const int tid = threadIdx.x;         // 256 threads
    const int ty  = tid >> 4;            // 0..15 -> rows ty*4..ty*4+3
    const int tx  = tid & 15;            // 0..15 -> edge cols tx*8..+7 / node cols tx*4..+3

    // ---- load s_i tile (transposed) and action tile (transposed) ----
    for (int idx = tid; idx < TB * DDIM; idx += 256) {
        int r = idx >> 6, d = idx & 63;                       // d fastest -> coalesced
        siT[d * PAD + r] = states[((size_t)(b0 + r) * KNODES + i) * DDIM + d];
    }
    for (int idx = tid; idx < TB * ADIM; idx += 256) {
        int r = idx >> 4, a = idx & 15;
        actT[a * PAD + r] = action[((size_t)(b0 + r) * KNODES + i) * ADIM + a];
    }

    // ---- edge loop: aggregate tanh(messages) over the 9 outgoing edges of node i ----
    float aggr[4][8];
    #pragma unroll
    for (int rr = 0; rr < 4; ++rr)
        #pragma unroll
        for (int cc = 0; cc < 8; ++cc) aggr[rr][cc] = 0.0f;

    for (int j = 0; j < KNODES; ++j) {
        if (j == i) continue;
        const int e = i * 9 + (j < i ? j : j - 1);

        __syncthreads();   // previous edge finished reading sjT / w_s

        // load s_j tile (transposed)
        for (int idx = tid; idx < TB * DDIM; idx += 256) {
            int r = idx >> 6, d = idx & 63;
            sjT[d * PAD + r] = states[((size_t)(b0 + r) * KNODES + j) * DDIM + d];
        }
        // load W_edge[e] : 128*128 floats = 4096 float4
        {
            const float4* wg = (const float4*)(W_edge + (size_t)e * (2 * DDIM * HDIM));
            float4* ws4 = (float4*)w_s;
            #pragma unroll 4
            for (int idx = tid; idx < 4096; idx += 256) ws4[idx] = wg[idx];
        }
        // bias for this edge (registers)
        float4 bl0 = *(const float4*)&b_edge[(size_t)e * HDIM + tx * 8];
        float4 bl1 = *(const float4*)&b_edge[(size_t)e * HDIM + tx * 8 + 4];

        __syncthreads();   // tiles ready

        float acc[4][8];
        #pragma unroll
        for (int rr = 0; rr < 4; ++rr) {
            acc[rr][0] = bl0.x; acc[rr][1] = bl0.y; acc[rr][2] = bl0.z; acc[rr][3] = bl0.w;
            acc[rr][4] = bl1.x; acc[rr][5] = bl1.y; acc[rr][6] = bl1.z; acc[rr][7] = bl1.w;
        }

        gemm_half(siT, w_s,                    acc, ty, tx);   // first 64 of concat (s_i)
        gemm_half(sjT, w_s + 64 * HDIM,        acc, ty, tx);   // second 64 (s_j)

        #pragma unroll
        for (int rr = 0; rr < 4; ++rr)
            #pragma unroll
            for (int cc = 0; cc < 8; ++cc)
                aggr[rr][cc] += tanhf(acc[rr][cc]);
    }

    __syncthreads();   // all threads done reading w_s before reuse

    // ---- stash agg (transposed) into smem ----
    #pragma unroll
    for (int rr = 0; rr < 4; ++rr)
        #pragma unroll
        for (int cc = 0; cc < 8; ++cc)
            aggT[(tx * 8 + cc) * PAD + (ty * 4 + rr)] = aggr[rr][cc];

    // ---- load W_node[i] : 208*64 floats = 3328 float4 ----
    {
        const float4* wg = (const float4*)(W_node + (size_t)i * FDIM * DDIM);
        float4* ws4 = (float4*)w_s;
        #pragma unroll
        for (int idx = tid; idx < 3328; idx += 256) ws4[idx] = wg[idx];
    }
    __syncthreads();

    // ---- node GEMM: [64 rows, 208] @ [208, 64] ----
    float acc2[4][4];
    {
        float4 bn = *(const float4*)&b_node[(size_t)i * DDIM + tx * 4];
        #pragma unroll
        for (int rr = 0; rr < 4; ++rr) {
            acc2[rr][0] = bn.x; acc2[rr][1] = bn.y; acc2[rr][2] = bn.z; acc2[rr][3] = bn.w;
        }
    }

    // f in [0,64): states part
    #pragma unroll 8
    for (int f = 0; f < 64; ++f) {
        float4 a4 = *(const float4*)&siT[f * PAD + ty * 4];
        float4 w4 = *(const float4*)&w_s[f * 64 + tx * 4];
        float av[4] = {a4.x, a4.y, a4.z, a4.w};
        float wv[4] = {w4.x, w4.y, w4.z, w4.w};
        #pragma unroll
        for (int rr = 0; rr < 4; ++rr)
            #pragma unroll
            for (int cc = 0; cc < 4; ++cc)
                acc2[rr][cc] = fmaf(av[rr], wv[cc], acc2[rr][cc]);
    }
    // f in [64,80): action part
    #pragma unroll
    for (int f = 0; f < 16; ++f) {
        float4 a4 = *(const float4*)&actT[f * PAD + ty * 4];
        float4 w4 = *(const float4*)&w_s[(64 + f) * 64 + tx * 4];
        float av[4] = {a4.x, a4.y, a4.z, a4.w};
        float wv[4] = {w4.x, w4.y, w4.z, w4.w};
        #pragma unroll
        for (int rr = 0; rr < 4; ++rr)
            #pragma unroll
            for (int cc = 0; cc < 4; ++cc)
                acc2[rr][cc] = fmaf(av[rr], wv[cc], acc2[rr][cc]);
    }
    // f in [80,208): agg part
    #pragma unroll 8
    for (int f = 0; f < 128; ++f) {
        float4 a4 = *(const float4*)&aggT[f * PAD + ty * 4];
        float4 w4 = *(const float4*)&w_s[(80 + f) * 64 + tx * 4];
        float av[4] = {a4.x, a4.y, a4.z, a4.w};
        float wv[4] = {w4.x, w4.y, w4.z, w4.w};
        #pragma unroll
        for (int rr = 0; rr < 4; ++rr)
            #pragma unroll
            for (int cc = 0; cc < 4; ++cc)
                acc2[rr][cc] = fmaf(av[rr], wv[cc], acc2[rr][cc]);
    }

    // ---- tanh + store ----
    #pragma unroll
    for (int rr = 0; rr < 4; ++rr) {
        int b = b0 + ty * 4 + rr;
        float4 o;
        o.x = tanhf(acc2[rr][0]);
        o.y = tanhf(acc2[rr][1]);
        o.z = tanhf(acc2[rr][2]);
        o.w = tanhf(acc2[rr][3]);
        *(float4*)&out[((size_t)b * KNODES + i) * DDIM + tx * 4] = o;
    }
}

extern "C" void kernel_launch(void* const* d_in, const int* in_sizes, int n_in,
                              void* d_out, int out_size)
{
    const float* states = (const float*)d_in[0];   // [B,K,D]
    const float* action = (const float*)d_in[1];   // [B,K,A]
    const float* W_edge = (const float*)d_in[2];   // [E,2D,H]
    const float* b_edge = (const float*)d_in[3];   // [E,H]
    const float* W_node = (const float*)d_in[4];   // [K,F,D]
    const float* b_node = (const float*)d_in[5];   // [K,D]
    float* out = (float*)d_out;

    int B = in_sizes[0] / (KNODES * DDIM);         // 8192

    size_t smem = (size_t)(64 * PAD + 64 * PAD + 128 * PAD + 16 * PAD) * sizeof(float)
                + (size_t)(2 * DDIM * HDIM) * sizeof(float);   // 139,520 B

    cudaFuncSetAttribute(gnn_fused_kernel,
                         cudaFuncAttributeMaxDynamicSharedMemorySize, (int)smem);

    dim3 grid(B / TB, KNODES);
    gnn_fused_kernel<<<grid, 256, smem>>>(states, action, W_edge, b_edge,
                                          W_node, b_node, out);
}

// round 2
// speedup vs baseline: 1.5457x; 1.5457x over previous
#include <cuda_runtime.h>
#include <cstdint>

// TransitionGNN fused, f32x2-packed FFMA version.
// B=8192, K=10, D=64, H=128, A=16, E=90, F=208.
// Block = (node i, 128 batch rows). 256 threads, 8x8 outputs/thread (edge GEMM),
// 8x4 (node GEMM). W_edge double-buffered via cp.async; W_node prefetched during
// last edge; aggT + W_node alias the W double-buffer after the edge loop.

#define KNODES 10
#define DDIM   64
#define HDIM   128
#define ADIM   16
#define TB     128
#define PADT   132   // transposed-tile row stride (floats), multiple of 4

typedef unsigned long long ull;

__device__ __forceinline__ ull ffma2(ull a, ull b, ull c) {
    ull d; asm("fma.rn.f32x2 %0, %1, %2, %3;" : "=l"(d) : "l"(a), "l"(b), "l"(c)); return d;
}
__device__ __forceinline__ ull pack2(float x, float y) {
    ull d; asm("mov.b64 %0, {%1, %2};" : "=l"(d) : "f"(x), "f"(y)); return d;
}
__device__ __forceinline__ void unpack2(ull v, float& x, float& y) {
    asm("mov.b64 {%0, %1}, %2;" : "=f"(x), "=f"(y) : "l"(v));
}
// tanh(x) = 1 - 2/(1+e^{2x});  ex2/rcp approx err ~1e-7 (abs), saturates correctly.
__device__ __forceinline__ float fast_tanh(float x) {
    float e, r;
    asm("ex2.approx.f32 %0, %1;" : "=f"(e) : "f"(x * 2.8853900817779268f));
    asm("rcp.approx.f32 %0, %1;" : "=f"(r) : "f"(e + 1.0f));
    return fmaf(-2.0f, r, 1.0f);
}
__device__ __forceinline__ void cp16(uint32_t s, const void* g) {
    asm volatile("cp.async.cg.shared.global [%0], [%1], 16;" :: "r"(s), "l"(g));
}

// 64-step K GEMM: aT [64][PADT] (k-major, row minor), w [64][HDIM].
// acc[rp][c] packs output rows (ty*8+2rp, ty*8+2rp+1), col tx*8+c.
__device__ __forceinline__ void gemm64(const float* __restrict__ aT,
                                       const float* __restrict__ w,
                                       ull acc[4][8], int ty, int tx)
{
    #pragma unroll 8
    for (int k = 0; k < 64; ++k) {
        const float* ar = aT + k * PADT + ty * 8;
        ulonglong2 a01 = *(const ulonglong2*)ar;        // rows 0-1, 2-3
        ulonglong2 a23 = *(const ulonglong2*)(ar + 4);  // rows 4-5, 6-7
        ull ap[4] = {a01.x, a01.y, a23.x, a23.y};
        const float* wr = w + k * HDIM + tx * 8;
        float4 w0 = *(const float4*)wr;
        float4 w1 = *(const float4*)(wr + 4);
        ull wd[8] = {pack2(w0.x, w0.x), pack2(w0.y, w0.y), pack2(w0.z, w0.z), pack2(w0.w, w0.w),
                     pack2(w1.x, w1.x), pack2(w1.y, w1.y), pack2(w1.z, w1.z), pack2(w1.w, w1.w)};
        #pragma unroll
        for (int rp = 0; rp < 4; ++rp)
            #pragma unroll
            for (int c = 0; c < 8; ++c)
                acc[rp][c] = ffma2(ap[rp], wd[c], acc[rp][c]);
    }
}

// Node GEMM partial: N f-steps, w [N][64] (col block tx*4..+3).
template <int N>
__device__ __forceinline__ void ngemm(const float* __restrict__ aT,
                                      const float* __restrict__ w,
                                      ull acc[4][4], int ty, int tx)
{
    #pragma unroll 8
    for (int f = 0; f < N; ++f) {
        const float* ar = aT + f * PADT + ty * 8;
        ulonglong2 a01 = *(const ulonglong2*)ar;
        ulonglong2 a23 = *(const ulonglong2*)(ar + 4);
        ull ap[4] = {a01.x, a01.y, a23.x, a23.y};
        float4 wv = *(const float4*)(w + f * 64 + tx * 4);
        ull wd[4] = {pack2(wv.x, wv.x), pack2(wv.y, wv.y), pack2(wv.z, wv.z), pack2(wv.w, wv.w)};
        #pragma unroll
        for (int rp = 0; rp < 4; ++rp)
            #pragma unroll
            for (int c = 0; c < 4; ++c)
                acc[rp][c] = ffma2(ap[rp], wd[c], acc[rp][c]);
    }
}

extern "C" __global__ void __launch_bounds__(256, 1)
gnn_f32x2_kernel(const float* __restrict__ states,   // [B,K,D]
                 const float* __restrict__ action,   // [B,K,A]
                 const float* __restrict__ W_edge,   // [E,2D,H]
                 const float* __restrict__ b_edge,   // [E,H]
                 const float* __restrict__ W_node,   // [K,F,D]
                 const float* __restrict__ b_node,   // [K,D]
                 float* __restrict__ out)            // [B,K,D]
{
    extern __shared__ float sm[];
    float* siT  = sm;                     // [64][PADT]   8448 f
    float* actT = siT  + 64 * PADT;       // [16][PADT]   2112 f
    float* sjT  = actT + 16 * PADT;       // [64][PADT]   8448 f
    float* wbuf = sjT  + 64 * PADT;       // 2 x 16384 f  (double-buffered edge W)
    float* aggT = wbuf;                   // alias: [128][PADT] = 16896 f (node phase)
    float* nw   = wbuf + 16896;           // alias: [208][64]  = 13312 f (node phase)

    const int i   = blockIdx.y;
    const int b0  = blockIdx.x * TB;
    const int tid = threadIdx.x;
    const int ty  = tid >> 4;     // 0..15 -> rows ty*8..+7
    const int tx  = tid & 15;     // 0..15 -> edge cols tx*8..+7 / node cols tx*4..+3

    // ---- prologue: s_i tile, action tile (transposed), prefetch W_edge[e0] ----
    for (int idx = tid; idx < TB * DDIM; idx += 256) {
        int r = idx >> 6, d = idx & 63;
        siT[d * PADT + r] = states[((size_t)(b0 + r) * KNODES + i) * DDIM + d];
    }
    for (int idx = tid; idx < TB * ADIM; idx += 256) {
        int r = idx >> 4, a = idx & 15;
        actT[a * PADT + r] = action[((size_t)(b0 + r) * KNODES + i) * ADIM + a];
    }
    {
        const float4* wg = (const float4*)(W_edge + (size_t)(i * 9) * (2 * DDIM * HDIM));
        uint32_t sdst = (uint32_t)__cvta_generic_to_shared(wbuf);
        #pragma unroll
        for (int q = 0; q < 16; ++q)
            cp16(sdst + (uint32_t)(tid + q * 256) * 16, wg + tid + q * 256);
        asm volatile("cp.async.commit_group;");
    }

    float aggr[8][8];
    #pragma unroll
    for (int r = 0; r < 8; ++r)
        #pragma unroll
        for (int c = 0; c < 8; ++c) aggr[r][c] = 0.0f;

    // ---- edge loop: 9 outgoing edges of node i (e = i*9 + t) ----
    for (int t = 0; t < 9; ++t) {
        const int jt = t + (t >= i);

        __syncthreads();   // GEMM t-1 done reading sjT and wbuf[(t+1)&1]

        // load s_j tile (transposed)
        for (int idx = tid; idx < TB * DDIM; idx += 256) {
            int r = idx >> 6, d = idx & 63;
            sjT[d * PADT + r] = states[((size_t)(b0 + r) * KNODES + jt) * DDIM + d];
        }
        // prefetch next edge W (or node W on the last iteration)
        if (t < 8) {
            const float4* wg = (const float4*)(W_edge + (size_t)(i * 9 + t + 1) * (2 * DDIM * HDIM));
            uint32_t sdst = (uint32_t)__cvta_generic_to_shared(wbuf + ((t + 1) & 1) * 16384);
            #pragma unroll
            for (int q = 0; q < 16; ++q)
                cp16(sdst + (uint32_t)(tid + q * 256) * 16, wg + tid + q * 256);
        } else {
            const float4* wg = (const float4*)(W_node + (size_t)i * (208 * 64));
            uint32_t sdst = (uint32_t)__cvta_generic_to_shared(nw);
            for (int q = tid; q < 3328; q += 256)
                cp16(sdst + (uint32_t)q * 16, wg + q);
        }
        asm volatile("cp.async.commit_group;");
        asm volatile("cp.async.wait_group 1;");   // current W tile complete

        // bias (registers)
        const float* be = b_edge + (size_t)(i * 9 + t) * HDIM + tx * 8;
        float4 bb0 = *(const float4*)be;
        float4 bb1 = *(const float4*)(be + 4);

        __syncthreads();   // sjT + W[t] visible to all

        ull acc[4][8];
        {
            ull bd[8] = {pack2(bb0.x, bb0.x), pack2(bb0.y, bb0.y), pack2(bb0.z, bb0.z), pack2(bb0.w, bb0.w),
                         pack2(bb1.x, bb1.x), pack2(bb1.y, bb1.y), pack2(bb1.z, bb1.z), pack2(bb1.w, bb1.w)};
            #pragma unroll
            for (int rp = 0; rp < 4; ++rp)
                #pragma unroll
                for (int c = 0; c < 8; ++c) acc[rp][c] = bd[c];
        }

        const float* wk = wbuf + (t & 1) * 16384;
        gemm64(siT, wk,              acc, ty, tx);   // s_i half
        gemm64(sjT, wk + 64 * HDIM,  acc, ty, tx);   // s_j half

        #pragma unroll
        for (int rp = 0; rp < 4; ++rp)
            #pragma unroll
            for (int c = 0; c < 8; ++c) {
                float lo, hi;
                unpack2(acc[rp][c], lo, hi);
                aggr[2 * rp + 0][c] += fast_tanh(lo);
                aggr[2 * rp + 1][c] += fast_tanh(hi);
            }
    }

    __syncthreads();   // last edge GEMM done reading wbuf[0]

    // stash agg (transposed) into aggT (aliases wbuf[0] region)
    #pragma unroll
    for (int r = 0; r < 8; ++r)
        #pragma unroll
        for (int c = 0; c < 8; ++c)
            aggT[(tx * 8 + c) * PADT + (ty * 8 + r)] = aggr[r][c];

    asm volatile("cp.async.wait_group 0;");   // W_node complete
    __syncthreads();

    // ---- node GEMM: [128 rows, 208] @ [208, 64] ----
    ull accN[4][4];
    {
        float4 bn = *(const float4*)(b_node + (size_t)i * DDIM + tx * 4);
        ull bd[4] = {pack2(bn.x, bn.x), pack2(bn.y, bn.y), pack2(bn.z, bn.z), pack2(bn.w, bn.w)};
        #pragma unroll
        for (int rp = 0; rp < 4; ++rp)
            #pragma unroll
            for (int c = 0; c < 4; ++c) accN[rp][c] = bd[c];
    }
    ngemm<64> (siT,  nw,           accN, ty, tx);   // states part
    ngemm<16> (actT, nw + 64 * 64, accN, ty, tx);   // action part
    ngemm<128>(aggT, nw + 80 * 64, accN, ty, tx);   // agg part

    // ---- tanh + store ----
    #pragma unroll
    for (int rp = 0; rp < 4; ++rp) {
        float o0[4], o1[4];
        #pragma unroll
        for (int c = 0; c < 4; ++c) {
            float lo, hi;
            unpack2(accN[rp][c], lo, hi);
            o0[c] = fast_tanh(lo);
            o1[c] = fast_tanh(hi);
        }
        int r0 = b0 + ty * 8 + 2 * rp;
        float4 v0 = {o0[0], o0[1], o0[2], o0[3]};
        float4 v1 = {o1[0], o1[1], o1[2], o1[3]};
        *(float4*)&out[((size_t)r0       * KNODES + i) * DDIM + tx * 4] = v0;
        *(float4*)&out[((size_t)(r0 + 1) * KNODES + i) * DDIM + tx * 4] = v1;
    }
}

extern "C" void kernel_launch(void* const* d_in, const int* in_sizes, int n_in,
                              void* d_out, int out_size)
{
    const float* states = (const float*)d_in[0];
    const float* action = (const float*)d_in[1];
    const float* W_edge = (const float*)d_in[2];
    const float* b_edge = (const float*)d_in[3];
    const float* W_node = (const float*)d_in[4];
    const float* b_node = (const float*)d_in[5];
    float* out = (float*)d_out;

    int B = in_sizes[0] / (KNODES * DDIM);   // 8192

    size_t smem = (size_t)(64 * PADT + 16 * PADT + 64 * PADT + 2 * 16384) * sizeof(float); // 207,104 B
    cudaFuncSetAttribute(gnn_f32x2_kernel,
                         cudaFuncAttributeMaxDynamicSharedMemorySize, (int)smem);

    dim3 grid(B / TB, KNODES);
    gnn_f32x2_kernel<<<grid, 256, smem>>>(states, action, W_edge, b_edge,
                                          W_node, b_node, out);
}

// round 5
// speedup vs baseline: 3.6445x; 2.3579x over previous
#include <cuda_runtime.h>
#include <cstdint>

// TransitionGNN via legacy HMMA mma.sync.m16n8k16 (bf16, 3-pass hi/lo split).
// B=8192, K=10, D=64, H=128, A=16, E=90, F=208.
// prep_kernel: stage all operands as bf16 hi/lo, pre-swizzled for ldmatrix.
// main kernel: block = (node i, 64 batch rows), 256 threads = 8 warps (4m x 2n).

#define KN 10
#define TB 64

// ---- staged scratch (bf16 hi/lo, ldmatrix-ready layouts) ----
__device__ __align__(16) unsigned char g_sHi[KN * 8192 * 128];   // [j][b][64d]  128B rows, swz
__device__ __align__(16) unsigned char g_sLo[KN * 8192 * 128];
__device__ __align__(16) unsigned char g_aHi[KN * 8192 * 48];    // [j][b][16a]  48B rows
__device__ __align__(16) unsigned char g_aLo[KN * 8192 * 48];
__device__ __align__(16) unsigned char g_WeHi[90 * 128 * 256];   // [e][128k][128h] 256B rows, swz
__device__ __align__(16) unsigned char g_WeLo[90 * 128 * 256];
__device__ __align__(16) unsigned char g_WnHi[KN * 208 * 128];   // [i][208f][64d] 128B rows, swz
__device__ __align__(16) unsigned char g_WnLo[KN * 208 * 128];

// ---- smem map (bytes) ----
#define SI_HI   0u
#define SI_LO   8192u
#define ACT_HI  16384u
#define ACT_LO  19456u
#define SJ_BASE 22528u          // 2 bufs x (hi 8KB + lo 8KB)
#define W_BASE  55296u          // 2 bufs x (hi 32KB + lo 32KB)
#define BIAS    186368u         // 128 f32
#define SMEM_TOTAL 186880
// node-phase aliases:
#define AGG_HI  22528u          // [64r][128k] 256B rows, swz
#define AGG_LO  38912u
#define WN_HI   120832u         // W buffer 1 region
#define WN_LO   147456u

__device__ __forceinline__ void split2(float x0, float x1, uint32_t& h2, uint32_t& l2) {
    asm("cvt.rn.bf16x2.f32 %0, %1, %2;" : "=r"(h2) : "f"(x1), "f"(x0));
    float h0 = __uint_as_float(h2 << 16);
    float h1 = __uint_as_float(h2 & 0xFFFF0000u);
    asm("cvt.rn.bf16x2.f32 %0, %1, %2;" : "=r"(l2) : "f"(x1 - h1), "f"(x0 - h0));
}
__device__ __forceinline__ float fast_tanh(float x) {
    float e, r;
    asm("ex2.approx.f32 %0, %1;" : "=f"(e) : "f"(x * 2.8853900817779268f));
    asm("rcp.approx.f32 %0, %1;" : "=f"(r) : "f"(e + 1.0f));
    return fmaf(-2.0f, r, 1.0f);
}
__device__ __forceinline__ void cp16(uint32_t s, const void* g) {
    asm volatile("cp.async.cg.shared.global [%0], [%1], 16;" :: "r"(s), "l"(g));
}
__device__ __forceinline__ void cpblk(uint32_t sdst, const void* gsrc, int bytes, int tid) {
    for (int off = tid * 16; off < bytes; off += 4096)
        cp16(sdst + off, (const char*)gsrc + off);
}
#define CP_COMMIT() asm volatile("cp.async.commit_group;")
#define CP_WAIT1()  asm volatile("cp.async.wait_group 1;")
#define CP_WAIT0()  asm volatile("cp.async.wait_group 0;")

__device__ __forceinline__ void ldsm4(uint32_t a, uint32_t r[4]) {
    asm volatile("ldmatrix.sync.aligned.m8n8.x4.shared.b16 {%0,%1,%2,%3}, [%4];"
        : "=r"(r[0]), "=r"(r[1]), "=r"(r[2]), "=r"(r[3]) : "r"(a));
}
__device__ __forceinline__ void ldsm4t(uint32_t a, uint32_t r[4]) {
    asm volatile("ldmatrix.sync.aligned.m8n8.x4.trans.shared.b16 {%0,%1,%2,%3}, [%4];"
        : "=r"(r[0]), "=r"(r[1]), "=r"(r[2]), "=r"(r[3]) : "r"(a));
}
__device__ __forceinline__ void mma(float c[4], const uint32_t a[4], uint32_t b0, uint32_t b1) {
    asm volatile("mma.sync.aligned.m16n8k16.row.col.f32.bf16.bf16.f32 "
        "{%0,%1,%2,%3},{%4,%5,%6,%7},{%8,%9},{%0,%1,%2,%3};"
        : "+f"(c[0]), "+f"(c[1]), "+f"(c[2]), "+f"(c[3])
        : "r"(a[0]), "r"(a[1]), "r"(a[2]), "r"(a[3]), "r"(b0), "r"(b1));
}
// ldmatrix address for swizzled tile: row = row0+(lane&15), chunk = (cs0+(lane>>4)) ^ (row&7)
__device__ __forceinline__ uint32_t ldsma(uint32_t base, int row0, int cs0, int stride, int lane) {
    int r = row0 + (lane & 15);
    return base + (uint32_t)(r * stride) + ((uint32_t)((cs0 + (lane >> 4)) ^ (r & 7)) << 4);
}

// ===================== prep kernel =====================
__global__ void prep_kernel(const float* __restrict__ states, const float* __restrict__ action,
                            const float* __restrict__ We, const float* __restrict__ Wn)
{
    int tid = blockIdx.x * blockDim.x + threadIdx.x;
    int NT  = gridDim.x * blockDim.x;
    // states: KN*8192*32 bf16 pairs  (row b, 128B, chunk swz with b&7)
    for (int p = tid; p < KN * 8192 * 32; p += NT) {
        int d2 = p & 31, b = (p >> 5) & 8191, j = p >> 18;
        float2 v = *(const float2*)&states[((size_t)b * KN + j) * 64 + 2 * d2];
        uint32_t h2, l2; split2(v.x, v.y, h2, l2);
        uint32_t off = ((uint32_t)(j * 8192 + b) << 7)
                     + ((uint32_t)(((d2 >> 2) ^ (b & 7))) << 4) + ((uint32_t)(d2 & 3) << 2);
        *(uint32_t*)(g_sHi + off) = h2;
        *(uint32_t*)(g_sLo + off) = l2;
    }
    // action: KN*8192*8 pairs (48B rows, no swz)
    for (int p = tid; p < KN * 8192 * 8; p += NT) {
        int a2 = p & 7, b = (p >> 3) & 8191, j = p >> 16;
        float2 v = *(const float2*)&action[((size_t)b * KN + j) * 16 + 2 * a2];
        uint32_t h2, l2; split2(v.x, v.y, h2, l2);
        uint32_t off = (uint32_t)(j * 8192 + b) * 48u + ((uint32_t)a2 << 2);
        *(uint32_t*)(g_aHi + off) = h2;
        *(uint32_t*)(g_aLo + off) = l2;
    }
    // W_edge: 90*128*64 pairs (row k, 256B, chunk swz with k&7)
    for (int p = tid; p < 90 * 128 * 64; p += NT) {
        int h2i = p & 63, k = (p >> 6) & 127, e = p >> 13;
        float2 v = *(const float2*)&We[((size_t)e * 128 + k) * 128 + 2 * h2i];
        uint32_t h2, l2; split2(v.x, v.y, h2, l2);
        uint32_t off = ((uint32_t)(e * 128 + k) << 8)
                     + ((uint32_t)(((h2i >> 2) ^ (k & 7))) << 4) + ((uint32_t)(h2i & 3) << 2);
        *(uint32_t*)(g_WeHi + off) = h2;
        *(uint32_t*)(g_WeLo + off) = l2;
    }
    // W_node: KN*208*32 pairs (row f, 128B, chunk swz with f&7)
    for (int p = tid; p < KN * 208 * 32; p += NT) {
        int d2 = p & 31, fi = p >> 5;
        int f = fi % 208, i = fi / 208;
        float2 v = *(const float2*)&Wn[((size_t)i * 208 + f) * 64 + 2 * d2];
        uint32_t h2, l2; split2(v.x, v.y, h2, l2);
        uint32_t off = ((uint32_t)(i * 208 + f) << 7)
                     + ((uint32_t)(((d2 >> 2) ^ (f & 7))) << 4) + ((uint32_t)(d2 & 3) << 2);
        *(uint32_t*)(g_WnHi + off) = h2;
        *(uint32_t*)(g_WnLo + off) = l2;
    }
}

// ===================== main kernel =====================
__device__ __forceinline__ void edge_k4(uint32_t aHi, uint32_t aLo, uint32_t wHi, uint32_t wLo,
                                        int ksBase, int m0, int wn, int lane, float C[32])
{
    #pragma unroll
    for (int kk = 0; kk < 4; ++kk) {
        uint32_t ah[4], al[4];
        ldsm4(ldsma(aHi, m0, 2 * kk, 128, lane), ah);
        ldsm4(ldsma(aLo, m0, 2 * kk, 128, lane), al);
        int krow = 16 * (ksBase + kk);
        #pragma unroll
        for (int p = 0; p < 4; ++p) {
            uint32_t bh[4], bl[4];
            ldsm4t(ldsma(wHi, krow, 8 * wn + 2 * p, 256, lane), bh);
            ldsm4t(ldsma(wLo, krow, 8 * wn + 2 * p, 256, lane), bl);
            float* c0 = C + (2 * p) * 4;
            float* c1 = C + (2 * p + 1) * 4;
            mma(c0, ah, bh[0], bh[1]); mma(c0, ah, bl[0], bl[1]); mma(c0, al, bh[0], bh[1]);
            mma(c1, ah, bh[2], bh[3]); mma(c1, ah, bl[2], bl[3]); mma(c1, al, bh[2], bh[3]);
        }
    }
}

__device__ __forceinline__ void node_step(uint32_t wnHi, uint32_t wnLo, int ks, int wn, int lane,
                                          const uint32_t ah[4], const uint32_t al[4], float C2[16])
{
    #pragma unroll
    for (int p = 0; p < 2; ++p) {
        uint32_t bh[4], bl[4];
        ldsm4t(ldsma(wnHi, 16 * ks, 4 * wn + 2 * p, 128, lane), bh);
        ldsm4t(ldsma(wnLo, 16 * ks, 4 * wn + 2 * p, 128, lane), bl);
        float* c0 = C2 + (2 * p) * 4;
        float* c1 = C2 + (2 * p + 1) * 4;
        mma(c0, ah, bh[0], bh[1]); mma(c0, ah, bl[0], bl[1]); mma(c0, al, bh[0], bh[1]);
        mma(c1, ah, bh[2], bh[3]); mma(c1, ah, bl[2], bl[3]); mma(c1, al, bh[2], bh[3]);
    }
}

extern "C" __global__ void __launch_bounds__(256, 1)
gnn_hmma_kernel(const float* __restrict__ b_edge,   // [E,H]
                const float* __restrict__ b_node,   // [K,D]
                float* __restrict__ out)            // [B,K,D]
{
    extern __shared__ char smem[];
    const uint32_t sb = (uint32_t)__cvta_generic_to_shared(smem);
    float* biasS = (float*)(smem + BIAS);

    const int i    = blockIdx.y;
    const int b0   = blockIdx.x * TB;
    const int tid  = threadIdx.x;
    const int lane = tid & 31;
    const int wid  = tid >> 5;
    const int wm   = wid & 3;    // 4 m-warps: rows 16*wm..+15
    const int wn   = wid >> 2;   // 2 n-warps: edge cols 64*wn..+63, node cols 32*wn..+31
    const int m0   = 16 * wm;

    // ---- prologue: G0 = {si, act, sj0, W0} ----
    cpblk(sb + SI_HI,  g_sHi + (size_t)(i * 8192 + b0) * 128, 8192, tid);
    cpblk(sb + SI_LO,  g_sLo + (size_t)(i * 8192 + b0) * 128, 8192, tid);
    cpblk(sb + ACT_HI, g_aHi + (size_t)(i * 8192 + b0) * 48,  3072, tid);
    cpblk(sb + ACT_LO, g_aLo + (size_t)(i * 8192 + b0) * 48,  3072, tid);
    {
        int j0 = (0 >= i) ? 1 : 0;   // j for t=0
        cpblk(sb + SJ_BASE,        g_sHi + (size_t)(j0 * 8192 + b0) * 128, 8192, tid);
        cpblk(sb + SJ_BASE + 8192, g_sLo + (size_t)(j0 * 8192 + b0) * 128, 8192, tid);
        cpblk(sb + W_BASE,         g_WeHi + (size_t)(i * 9) * 32768, 32768, tid);
        cpblk(sb + W_BASE + 32768, g_WeLo + (size_t)(i * 9) * 32768, 32768, tid);
    }
    CP_COMMIT();

    float agg[32];
    #pragma unroll
    for (int q = 0; q < 32; ++q) agg[q] = 0.0f;

    // ---- edge loop ----
    for (int t = 0; t < 9; ++t) {
        const int e = i * 9 + t;

        // prefetch next (G_{t+1}) or W_node (G9)
        if (t < 8) {
            int jn = (t + 1) + ((t + 1) >= i ? 1 : 0);
            uint32_t sj = SJ_BASE + ((t + 1) & 1) * 16384u;
            uint32_t wb = W_BASE + ((t + 1) & 1) * 65536u;
            cpblk(sb + sj,         g_sHi + (size_t)(jn * 8192 + b0) * 128, 8192, tid);
            cpblk(sb + sj + 8192,  g_sLo + (size_t)(jn * 8192 + b0) * 128, 8192, tid);
            cpblk(sb + wb,         g_WeHi + (size_t)(e + 1) * 32768, 32768, tid);
            cpblk(sb + wb + 32768, g_WeLo + (size_t)(e + 1) * 32768, 32768, tid);
        } else {
            cpblk(sb + WN_HI, g_WnHi + (size_t)i * 26624, 26624, tid);
            cpblk(sb + WN_LO, g_WnLo + (size_t)i * 26624, 26624, tid);
        }
        CP_COMMIT();

        if (tid < 128) biasS[tid] = b_edge[(size_t)e * 128 + tid];

        CP_WAIT1();          // G_t complete
        __syncthreads();     // all tiles + bias visible

        float C[32];
        #pragma unroll
        for (int q = 0; q < 32; ++q) C[q] = 0.0f;

        uint32_t sjHi = sb + SJ_BASE + (t & 1) * 16384u;
        uint32_t wHi  = sb + W_BASE + (t & 1) * 65536u;
        edge_k4(sb + SI_HI, sb + SI_LO, wHi, wHi + 32768u, 0, m0, wn, lane, C);   // s_i half
        edge_k4(sjHi, sjHi + 8192u,     wHi, wHi + 32768u, 4, m0, wn, lane, C);   // s_j half

        // epilogue: agg += tanh(C + bias)
        #pragma unroll
        for (int nb = 0; nb < 8; ++nb) {
            int h = 64 * wn + 8 * nb + (lane & 3) * 2;
            float bv0 = biasS[h], bv1 = biasS[h + 1];
            agg[nb * 4 + 0] += fast_tanh(C[nb * 4 + 0] + bv0);
            agg[nb * 4 + 1] += fast_tanh(C[nb * 4 + 1] + bv1);
            agg[nb * 4 + 2] += fast_tanh(C[nb * 4 + 2] + bv0);
            agg[nb * 4 + 3] += fast_tanh(C[nb * 4 + 3] + bv1);
        }
        __syncthreads();     // buffer reuse + bias protection
    }

    // ---- node phase: write agg as bf16 hi/lo A-tile [64r][128k] ----
    #pragma unroll
    for (int nb = 0; nb < 8; ++nb) {
        int h = 64 * wn + 8 * nb + (lane & 3) * 2;
        #pragma unroll
        for (int hh = 0; hh < 2; ++hh) {
            int r = m0 + (lane >> 2) + 8 * hh;
            uint32_t h2, l2;
            split2(agg[nb * 4 + 2 * hh], agg[nb * 4 + 2 * hh + 1], h2, l2);
            uint32_t off = (uint32_t)(r * 256) + ((uint32_t)(((h >> 3) ^ (r & 7))) << 4)
                         + ((uint32_t)(h & 7) << 1);
            *(uint32_t*)(smem + AGG_HI + off) = h2;
            *(uint32_t*)(smem + AGG_LO + off) = l2;
        }
    }
    CP_WAIT0();          // W_node staged
    __syncthreads();

    float C2[16];
    #pragma unroll
    for (int q = 0; q < 16; ++q) C2[q] = 0.0f;

    // f 0..63: states
    #pragma unroll
    for (int ks = 0; ks < 4; ++ks) {
        uint32_t ah[4], al[4];
        ldsm4(ldsma(sb + SI_HI, m0, 2 * ks, 128, lane), ah);
        ldsm4(ldsma(sb + SI_LO, m0, 2 * ks, 128, lane), al);
        node_step(sb + WN_HI, sb + WN_LO, ks, wn, lane, ah, al, C2);
    }
    // f 64..79: action (48B rows, no swizzle)
    {
        uint32_t ah[4], al[4];
        int r = m0 + (lane & 15);
        uint32_t ao = (uint32_t)(r * 48) + ((uint32_t)(lane >> 4) << 4);
        ldsm4(sb + ACT_HI + ao, ah);
        ldsm4(sb + ACT_LO + ao, al);
        node_step(sb + WN_HI, sb + WN_LO, 4, wn, lane, ah, al, C2);
    }
    // f 80..207: agg
    #pragma unroll
    for (int ks = 5; ks < 13; ++ks) {
        uint32_t ah[4], al[4];
        ldsm4(ldsma(sb + AGG_HI, m0, 2 * (ks - 5), 256, lane), ah);
        ldsm4(ldsma(sb + AGG_LO, m0, 2 * (ks - 5), 256, lane), al);
        node_step(sb + WN_HI, sb + WN_LO, ks, wn, lane, ah, al, C2);
    }

    // ---- final epilogue: tanh + store ----
    #pragma unroll
    for (int nb = 0; nb < 4; ++nb) {
        int d = 32 * wn + 8 * nb + (lane & 3) * 2;
        float2 bn = *(const float2*)&b_node[(size_t)i * 64 + d];
        int r0 = m0 + (lane >> 2);
        float2 v0 = { fast_tanh(C2[nb * 4 + 0] + bn.x), fast_tanh(C2[nb * 4 + 1] + bn.y) };
        float2 v1 = { fast_tanh(C2[nb * 4 + 2] + bn.x), fast_tanh(C2[nb * 4 + 3] + bn.y) };
        *(float2*)&out[((size_t)(b0 + r0)     * KN + i) * 64 + d] = v0;
        *(float2*)&out[((size_t)(b0 + r0 + 8) * KN + i) * 64 + d] = v1;
    }
}

extern "C" void kernel_launch(void* const* d_in, const int* in_sizes, int n_in,
                              void* d_out, int out_size)
{
    const float* states = (const float*)d_in[0];
    const float* action = (const float*)d_in[1];
    const float* W_edge = (const float*)d_in[2];
    const float* b_edge = (const float*)d_in[3];
    const float* W_node = (const float*)d_in[4];
    const float* b_node = (const float*)d_in[5];
    float* out = (float*)d_out;

    int B = in_sizes[0] / (KN * 64);   // 8192

    prep_kernel<<<2048, 256>>>(states, action, W_edge, W_node);

    cudaFuncSetAttribute(gnn_hmma_kernel,
                         cudaFuncAttributeMaxDynamicSharedMemorySize, SMEM_TOTAL);
    dim3 grid(B / TB, KN);
    gnn_hmma_kernel<<<grid, 256, SMEM_TOTAL>>>(b_edge, b_node, out);
}

// round 6
// speedup vs baseline: 3.6707x; 1.0072x over previous
#include <cuda_runtime.h>
#include <cstdint>

// TransitionGNN via legacy HMMA mma.sync.m16n8k16 (bf16, 3-pass hi/lo split),
// with software-pipelined tanh epilogue (MUFU overlapped with tensor pipe).
// B=8192, K=10, D=64, H=128, A=16, E=90, F=208.
// prep_kernel: stage operands as bf16 hi/lo (pre-swizzled), W/b pre-scaled by 2/ln2.
// main kernel: block = (node i, 64 batch rows), 256 threads = 8 warps (4m x 2n).

#define KN 10
#define TB 64
#define L2E2 2.8853900817779268f   // 2/ln(2): tanh(z) = 1 - 2/(1+exp2(L2E2*z))

// ---- staged scratch ----
__device__ __align__(16) unsigned char g_sHi[KN * 8192 * 128];   // [j][b][64d]  128B rows, swz
__device__ __align__(16) unsigned char g_sLo[KN * 8192 * 128];
__device__ __align__(16) unsigned char g_aHi[KN * 8192 * 48];    // [j][b][16a]  48B rows
__device__ __align__(16) unsigned char g_aLo[KN * 8192 * 48];
__device__ __align__(16) unsigned char g_WeHi[90 * 128 * 256];   // [e][128k][128h] 256B rows, swz (scaled)
__device__ __align__(16) unsigned char g_WeLo[90 * 128 * 256];
__device__ __align__(16) unsigned char g_WnHi[KN * 208 * 128];   // [i][208f][64d] 128B rows, swz (scaled)
__device__ __align__(16) unsigned char g_WnLo[KN * 208 * 128];
__device__ __align__(16) float g_be2[90 * 128];                  // scaled edge bias
__device__ __align__(16) float g_bn2[KN * 64];                   // scaled node bias

// ---- smem map (bytes) ----
#define SI_HI   0u
#define SI_LO   8192u
#define ACT_HI  16384u
#define ACT_LO  19456u
#define SJ_BASE 22528u          // 2 bufs x (hi 8KB + lo 8KB)
#define W_BASE  55296u          // 2 bufs x (hi 32KB + lo 32KB)
#define BIAS    186368u         // 2 slots x 512B (f32, scaled)
#define SMEM_TOTAL 187392
// node-phase aliases:
#define AGG_HI  22528u          // [64r][128k] 256B rows, swz
#define AGG_LO  38912u
#define WN_HI   120832u         // in W buffer-1 region (edge 8 uses buffer 0)
#define WN_LO   147456u

__device__ __forceinline__ void split2(float x0, float x1, uint32_t& h2, uint32_t& l2) {
    asm("cvt.rn.bf16x2.f32 %0, %1, %2;" : "=r"(h2) : "f"(x1), "f"(x0));
    float h0 = __uint_as_float(h2 << 16);
    float h1 = __uint_as_float(h2 & 0xFFFF0000u);
    asm("cvt.rn.bf16x2.f32 %0, %1, %2;" : "=r"(l2) : "f"(x1 - h1), "f"(x0 - h0));
}
// z pre-scaled by 2/ln2: returns rcp(1 + 2^z); tanh = 1 - 2*r
__device__ __forceinline__ float tanh_r(float z) {
    float e, r;
    asm("ex2.approx.f32 %0, %1;" : "=f"(e) : "f"(z));
    asm("rcp.approx.f32 %0, %1;" : "=f"(r) : "f"(e + 1.0f));
    return r;
}
__device__ __forceinline__ void cp16(uint32_t s, const void* g) {
    asm volatile("cp.async.cg.shared.global [%0], [%1], 16;" :: "r"(s), "l"(g));
}
__device__ __forceinline__ void cpblk(uint32_t sdst, const void* gsrc, int bytes, int tid) {
    for (int off = tid * 16; off < bytes; off += 4096)
        cp16(sdst + off, (const char*)gsrc + off);
}
#define CP_COMMIT() asm volatile("cp.async.commit_group;")
#define CP_WAIT1()  asm volatile("cp.async.wait_group 1;")
#define CP_WAIT0()  asm volatile("cp.async.wait_group 0;")

__device__ __forceinline__ void ldsm4(uint32_t a, uint32_t r[4]) {
    asm volatile("ldmatrix.sync.aligned.m8n8.x4.shared.b16 {%0,%1,%2,%3}, [%4];"
        : "=r"(r[0]), "=r"(r[1]), "=r"(r[2]), "=r"(r[3]) : "r"(a));
}
__device__ __forceinline__ void ldsm4t(uint32_t a, uint32_t r[4]) {
    asm volatile("ldmatrix.sync.aligned.m8n8.x4.trans.shared.b16 {%0,%1,%2,%3}, [%4];"
        : "=r"(r[0]), "=r"(r[1]), "=r"(r[2]), "=r"(r[3]) : "r"(a));
}
__device__ __forceinline__ void mma(float c[4], const uint32_t a[4], uint32_t b0, uint32_t b1) {
    asm volatile("mma.sync.aligned.m16n8k16.row.col.f32.bf16.bf16.f32 "
        "{%0,%1,%2,%3},{%4,%5,%6,%7},{%8,%9},{%0,%1,%2,%3};"
        : "+f"(c[0]), "+f"(c[1]), "+f"(c[2]), "+f"(c[3])
        : "r"(a[0]), "r"(a[1]), "r"(a[2]), "r"(a[3]), "r"(b0), "r"(b1));
}
__device__ __forceinline__ uint32_t ldsma(uint32_t base, int row0, int cs0, int stride, int lane) {
    int r = row0 + (lane & 15);
    return base + (uint32_t)(r * stride) + ((uint32_t)((cs0 + (lane >> 4)) ^ (r & 7)) << 4);
}

// ===================== prep kernel =====================
__global__ void prep_kernel(const float* __restrict__ states, const float* __restrict__ action,
                            const float* __restrict__ We, const float* __restrict__ be,
                            const float* __restrict__ Wn, const float* __restrict__ bn)
{
    int tid = blockIdx.x * blockDim.x + threadIdx.x;
    int NT  = gridDim.x * blockDim.x;
    for (int p = tid; p < KN * 8192 * 32; p += NT) {
        int d2 = p & 31, b = (p >> 5) & 8191, j = p >> 18;
        float2 v = *(const float2*)&states[((size_t)b * KN + j) * 64 + 2 * d2];
        uint32_t h2, l2; split2(v.x, v.y, h2, l2);
        uint32_t off = ((uint32_t)(j * 8192 + b) << 7)
                     + ((uint32_t)(((d2 >> 2) ^ (b & 7))) << 4) + ((uint32_t)(d2 & 3) << 2);
        *(uint32_t*)(g_sHi + off) = h2;
        *(uint32_t*)(g_sLo + off) = l2;
    }
    for (int p = tid; p < KN * 8192 * 8; p += NT) {
        int a2 = p & 7, b = (p >> 3) & 8191, j = p >> 16;
        float2 v = *(const float2*)&action[((size_t)b * KN + j) * 16 + 2 * a2];
        uint32_t h2, l2; split2(v.x, v.y, h2, l2);
        uint32_t off = (uint32_t)(j * 8192 + b) * 48u + ((uint32_t)a2 << 2);
        *(uint32_t*)(g_aHi + off) = h2;
        *(uint32_t*)(g_aLo + off) = l2;
    }
    for (int p = tid; p < 90 * 128 * 64; p += NT) {
        int h2i = p & 63, k = (p >> 6) & 127, e = p >> 13;
        float2 v = *(const float2*)&We[((size_t)e * 128 + k) * 128 + 2 * h2i];
        uint32_t h2, l2; split2(L2E2 * v.x, L2E2 * v.y, h2, l2);
        uint32_t off = ((uint32_t)(e * 128 + k) << 8)
                     + ((uint32_t)(((h2i >> 2) ^ (k & 7))) << 4) + ((uint32_t)(h2i & 3) << 2);
        *(uint32_t*)(g_WeHi + off) = h2;
        *(uint32_t*)(g_WeLo + off) = l2;
    }
    for (int p = tid; p < KN * 208 * 32; p += NT) {
        int d2 = p & 31, fi = p >> 5;
        int f = fi % 208, i = fi / 208;
        float2 v = *(const float2*)&Wn[((size_t)i * 208 + f) * 64 + 2 * d2];
        uint32_t h2, l2; split2(L2E2 * v.x, L2E2 * v.y, h2, l2);
        uint32_t off = ((uint32_t)(i * 208 + f) << 7)
                     + ((uint32_t)(((d2 >> 2) ^ (f & 7))) << 4) + ((uint32_t)(d2 & 3) << 2);
        *(uint32_t*)(g_WnHi + off) = h2;
        *(uint32_t*)(g_WnLo + off) = l2;
    }
    for (int p = tid; p < 90 * 128; p += NT) g_be2[p] = L2E2 * be[p];
    for (int p = tid; p < KN * 64;  p += NT) g_bn2[p] = L2E2 * bn[p];
}

// ===================== main kernel =====================
__device__ __forceinline__ void node_step(uint32_t wnHi, uint32_t wnLo, int ks, int wn, int lane,
                                          const uint32_t ah[4], const uint32_t al[4], float C2[16])
{
    #pragma unroll
    for (int p = 0; p < 2; ++p) {
        uint32_t bh[4], bl[4];
        ldsm4t(ldsma(wnHi, 16 * ks, 4 * wn + 2 * p, 128, lane), bh);
        ldsm4t(ldsma(wnLo, 16 * ks, 4 * wn + 2 * p, 128, lane), bl);
        float* c0 = C2 + (2 * p) * 4;
        float* c1 = C2 + (2 * p + 1) * 4;
        mma(c0, ah, bh[0], bh[1]); mma(c0, ah, bl[0], bl[1]); mma(c0, al, bh[0], bh[1]);
        mma(c1, ah, bh[2], bh[3]); mma(c1, ah, bl[2], bl[3]); mma(c1, al, bh[2], bh[3]);
    }
}

extern "C" __global__ void __launch_bounds__(256, 1)
gnn_hmma_kernel(float* __restrict__ out)            // [B,K,D]
{
    extern __shared__ char smem[];
    const uint32_t sb = (uint32_t)__cvta_generic_to_shared(smem);

    const int i    = blockIdx.y;
    const int b0   = blockIdx.x * TB;
    const int tid  = threadIdx.x;
    const int lane = tid & 31;
    const int wid  = tid >> 5;
    const int wm   = wid & 3;    // 4 m-warps: rows 16*wm..+15
    const int wn   = wid >> 2;   // 2 n-warps: edge cols 64*wn..+63, node cols 32*wn..+31
    const int m0   = 16 * wm;

    // ---- prologue: G0 = {si, act, sj0, W0, bias0} ----
    cpblk(sb + SI_HI,  g_sHi + (size_t)(i * 8192 + b0) * 128, 8192, tid);
    cpblk(sb + SI_LO,  g_sLo + (size_t)(i * 8192 + b0) * 128, 8192, tid);
    cpblk(sb + ACT_HI, g_aHi + (size_t)(i * 8192 + b0) * 48,  3072, tid);
    cpblk(sb + ACT_LO, g_aLo + (size_t)(i * 8192 + b0) * 48,  3072, tid);
    {
        int j0 = (i == 0) ? 1 : 0;
        cpblk(sb + SJ_BASE,        g_sHi + (size_t)(j0 * 8192 + b0) * 128, 8192, tid);
        cpblk(sb + SJ_BASE + 8192, g_sLo + (size_t)(j0 * 8192 + b0) * 128, 8192, tid);
        cpblk(sb + W_BASE,         g_WeHi + (size_t)(i * 9) * 32768, 32768, tid);
        cpblk(sb + W_BASE + 32768, g_WeLo + (size_t)(i * 9) * 32768, 32768, tid);
        if (tid < 32) cp16(sb + BIAS + tid * 16, (const char*)(g_be2 + (size_t)(i * 9) * 128) + tid * 16);
    }
    CP_COMMIT();

    float Ca[32], Cb[32], agg2[32];
    #pragma unroll
    for (int q = 0; q < 32; ++q) agg2[q] = 0.0f;

    // ---- edge loop (fully unrolled; epilogue of edge t-1 interleaved into edge t's MMAs) ----
    #pragma unroll
    for (int t = 0; t < 9; ++t) {
        float* C  = (t & 1) ? Cb : Ca;
        float* Cp = (t & 1) ? Ca : Cb;
        const int e = i * 9 + t;

        // prefetch next tiles (or W_node on last iteration)
        if (t < 8) {
            int jn = (t + 1) + ((t + 1) >= i ? 1 : 0);
            uint32_t sj = SJ_BASE + ((t + 1) & 1) * 16384u;
            uint32_t wb = W_BASE + ((t + 1) & 1) * 65536u;
            cpblk(sb + sj,         g_sHi + (size_t)(jn * 8192 + b0) * 128, 8192, tid);
            cpblk(sb + sj + 8192,  g_sLo + (size_t)(jn * 8192 + b0) * 128, 8192, tid);
            cpblk(sb + wb,         g_WeHi + (size_t)(e + 1) * 32768, 32768, tid);
            cpblk(sb + wb + 32768, g_WeLo + (size_t)(e + 1) * 32768, 32768, tid);
            if (tid < 32)
                cp16(sb + BIAS + ((t + 1) & 1) * 512 + tid * 16,
                     (const char*)(g_be2 + (size_t)(e + 1) * 128) + tid * 16);
        } else {
            cpblk(sb + WN_HI, g_WnHi + (size_t)i * 26624, 26624, tid);
            cpblk(sb + WN_LO, g_WnLo + (size_t)i * 26624, 26624, tid);
        }
        CP_COMMIT();
        CP_WAIT1();          // tiles for edge t complete
        __syncthreads();

        // init C from (pre-scaled) bias
        {
            const float* bs = (const float*)(smem + BIAS + (t & 1) * 512);
            #pragma unroll
            for (int nb = 0; nb < 8; ++nb) {
                int h = 64 * wn + 8 * nb + (lane & 3) * 2;
                float b0v = bs[h], b1v = bs[h + 1];
                C[nb * 4 + 0] = b0v; C[nb * 4 + 1] = b1v;
                C[nb * 4 + 2] = b0v; C[nb * 4 + 3] = b1v;
            }
        }

        uint32_t sjHi = sb + SJ_BASE + (t & 1) * 16384u;
        uint32_t wHi  = sb + W_BASE + (t & 1) * 65536u;
        uint32_t wLo  = wHi + 32768u;

        #pragma unroll
        for (int kk = 0; kk < 8; ++kk) {
            uint32_t aHiB = (kk < 4) ? (sb + SI_HI) : sjHi;
            uint32_t aLoB = (kk < 4) ? (sb + SI_LO) : (sjHi + 8192u);
            int kl = kk & 3;
            uint32_t ah[4], al[4];
            ldsm4(ldsma(aHiB, m0, 2 * kl, 128, lane), ah);
            ldsm4(ldsma(aLoB, m0, 2 * kl, 128, lane), al);
            int krow = 16 * kk;
            #pragma unroll
            for (int p = 0; p < 4; ++p) {
                uint32_t bh[4], bl[4];
                ldsm4t(ldsma(wHi, krow, 8 * wn + 2 * p, 256, lane), bh);
                ldsm4t(ldsma(wLo, krow, 8 * wn + 2 * p, 256, lane), bl);
                float* c0 = C + (2 * p) * 4;
                float* c1 = C + (2 * p + 1) * 4;
                mma(c0, ah, bh[0], bh[1]); mma(c0, ah, bl[0], bl[1]); mma(c0, al, bh[0], bh[1]);
                mma(c1, ah, bh[2], bh[3]); mma(c1, ah, bl[2], bl[3]); mma(c1, al, bh[2], bh[3]);
            }
            // interleaved epilogue slice of edge t-1: 4 values (overlaps MUFU with tensor)
            if (t > 0) {
                #pragma unroll
                for (int q = 0; q < 4; ++q) {
                    float r = tanh_r(Cp[kk * 4 + q]);
                    agg2[kk * 4 + q] = fmaf(-2.0f, r, agg2[kk * 4 + q]);
                }
            }
        }
        __syncthreads();     // tiles of edge t fully consumed before prefetch overwrite
    }

    // final epilogue for edge 8 (C in Ca: t=8 even)
    #pragma unroll
    for (int q = 0; q < 32; ++q) {
        float r = tanh_r(Ca[q]);
        agg2[q] = fmaf(-2.0f, r, agg2[q]);
    }

    // ---- node phase: agg = 9 + agg2 -> bf16 hi/lo A-tile [64r][128k] ----
    #pragma unroll
    for (int nb = 0; nb < 8; ++nb) {
        int h = 64 * wn + 8 * nb + (lane & 3) * 2;
        #pragma unroll
        for (int hh = 0; hh < 2; ++hh) {
            int r = m0 + (lane >> 2) + 8 * hh;
            uint32_t h2, l2;
            split2(9.0f + agg2[nb * 4 + 2 * hh], 9.0f + agg2[nb * 4 + 2 * hh + 1], h2, l2);
            uint32_t off = (uint32_t)(r * 256) + ((uint32_t)(((h >> 3) ^ (r & 7))) << 4)
                         + ((uint32_t)(h & 7) << 1);
            *(uint32_t*)(smem + AGG_HI + off) = h2;
            *(uint32_t*)(smem + AGG_LO + off) = l2;
        }
    }
    CP_WAIT0();          // W_node staged
    __syncthreads();

    // init C2 from (pre-scaled) node bias
    float C2[16];
    #pragma unroll
    for (int nb = 0; nb < 4; ++nb) {
        int d = 32 * wn + 8 * nb + (lane & 3) * 2;
        float2 bn = *(const float2*)&g_bn2[(size_t)i * 64 + d];
        C2[nb * 4 + 0] = bn.x; C2[nb * 4 + 1] = bn.y;
        C2[nb * 4 + 2] = bn.x; C2[nb * 4 + 3] = bn.y;
    }

    // f 0..63: states
    #pragma unroll
    for (int ks = 0; ks < 4; ++ks) {
        uint32_t ah[4], al[4];
        ldsm4(ldsma(sb + SI_HI, m0, 2 * ks, 128, lane), ah);
        ldsm4(ldsma(sb + SI_LO, m0, 2 * ks, 128, lane), al);
        node_step(sb + WN_HI, sb + WN_LO, ks, wn, lane, ah, al, C2);
    }
    // f 64..79: action (48B rows, no swizzle)
    {
        uint32_t ah[4], al[4];
        int r = m0 + (lane & 15);
        uint32_t ao = (uint32_t)(r * 48) + ((uint32_t)(lane >> 4) << 4);
        ldsm4(sb + ACT_HI + ao, ah);
        ldsm4(sb + ACT_LO + ao, al);
        node_step(sb + WN_HI, sb + WN_LO, 4, wn, lane, ah, al, C2);
    }
    // f 80..207: agg
    #pragma unroll
    for (int ks = 5; ks < 13; ++ks) {
        uint32_t ah[4], al[4];
        ldsm4(ldsma(sb + AGG_HI, m0, 2 * (ks - 5), 256, lane), ah);
        ldsm4(ldsma(sb + AGG_LO, m0, 2 * (ks - 5), 256, lane), al);
        node_step(sb + WN_HI, sb + WN_LO, ks, wn, lane, ah, al, C2);
    }

    // ---- final epilogue: tanh = 1 - 2*rcp(1+ex2(C2)), store ----
    #pragma unroll
    for (int nb = 0; nb < 4; ++nb) {
        int d = 32 * wn + 8 * nb + (lane & 3) * 2;
        int r0 = m0 + (lane >> 2);
        float2 v0, v1;
        v0.x = fmaf(-2.0f, tanh_r(C2[nb * 4 + 0]), 1.0f);
        v0.y = fmaf(-2.0f, tanh_r(C2[nb * 4 + 1]), 1.0f);
        v1.x = fmaf(-2.0f, tanh_r(C2[nb * 4 + 2]), 1.0f);
        v1.y = fmaf(-2.0f, tanh_r(C2[nb * 4 + 3]), 1.0f);
        *(float2*)&out[((size_t)(b0 + r0)     * KN + i) * 64 + d] = v0;
        *(float2*)&out[((size_t)(b0 + r0 + 8) * KN + i) * 64 + d] = v1;
    }
}

extern "C" void kernel_launch(void* const* d_in, const int* in_sizes, int n_in,
                              void* d_out, int out_size)
{
    const float* states = (const float*)d_in[0];
    const float* action = (const float*)d_in[1];
    const float* W_edge = (const float*)d_in[2];
    const float* b_edge = (const float*)d_in[3];
    const float* W_node = (const float*)d_in[4];
    const float* b_node = (const float*)d_in[5];
    float* out = (float*)d_out;

    int B = in_sizes[0] / (KN * 64);   // 8192

    prep_kernel<<<2048, 256>>>(states, action, W_edge, b_edge, W_node, b_node);

    cudaFuncSetAttribute(gnn_hmma_kernel,
                         cudaFuncAttributeMaxDynamicSharedMemorySize, SMEM_TOTAL);
    dim3 grid(B / TB, KN);
    gnn_hmma_kernel<<<grid, 256, SMEM_TOTAL>>>(out);
}

// round 7
// speedup vs baseline: 4.1802x; 1.1388x over previous
#include <cuda_runtime.h>
#include <cstdint>

// TransitionGNN via legacy HMMA mma.sync.m16n8k16 (bf16, 3-pass hi/lo split).
// R7: TB=128 batch rows/block, warp tile M32xN64 (halves ldsm traffic/MMA),
// pass-reordered MMAs (RAW spacing 16), tanh.approx epilogue (1 MUFU/value).
// B=8192, K=10, D=64, H=128, A=16, E=90, F=208.

#define KN 10
#define TB 128

// ---- staged scratch (bf16 hi/lo, ldmatrix-ready) ----
__device__ __align__(16) unsigned char g_sHi[KN * 8192 * 128];   // [j][b][64d] 128B rows, swz
__device__ __align__(16) unsigned char g_sLo[KN * 8192 * 128];
__device__ __align__(16) unsigned char g_aHi[KN * 8192 * 32];    // [j][b][16a] 32B rows
__device__ __align__(16) unsigned char g_aLo[KN * 8192 * 32];
__device__ __align__(16) unsigned char g_WeHi[90 * 128 * 256];   // [e][128k][128h] 256B rows, swz
__device__ __align__(16) unsigned char g_WeLo[90 * 128 * 256];
__device__ __align__(16) unsigned char g_WnHi[KN * 208 * 128];   // [i][208f][64d] 128B rows, swz
__device__ __align__(16) unsigned char g_WnLo[KN * 208 * 128];

// ---- smem map (bytes) ----
#define SI_HI    0u
#define SI_LO    16384u
#define ACT_HI   32768u
#define ACT_LO   36864u
#define SJ_HI    40960u
#define SJ_LO    57344u
#define W0       73728u         // 2 bufs x (hi 32KB + lo 32KB)
#define BIASALL  204800u        // 9 x 512B f32
#define SMEM_TOTAL 209920
// node-phase aliases:
#define AGG_HI   73728u         // [128r][256B] swz  (W buf 0)
#define AGG_LO   106496u
#define WN_HI    139264u        // (W buf 1)
#define WN_LO    165888u

__device__ __forceinline__ void split2(float x0, float x1, uint32_t& h2, uint32_t& l2) {
    asm("cvt.rn.bf16x2.f32 %0, %1, %2;" : "=r"(h2) : "f"(x1), "f"(x0));
    float h0 = __uint_as_float(h2 << 16);
    float h1 = __uint_as_float(h2 & 0xFFFF0000u);
    asm("cvt.rn.bf16x2.f32 %0, %1, %2;" : "=r"(l2) : "f"(x1 - h1), "f"(x0 - h0));
}
__device__ __forceinline__ float tanha(float x) {
    float r; asm("tanh.approx.f32 %0, %1;" : "=f"(r) : "f"(x)); return r;
}
__device__ __forceinline__ void cp16(uint32_t s, const void* g) {
    asm volatile("cp.async.cg.shared.global [%0], [%1], 16;" :: "r"(s), "l"(g));
}
__device__ __forceinline__ void cpblk(uint32_t sdst, const void* gsrc, int bytes, int tid) {
    for (int off = tid * 16; off < bytes; off += 4096)
        cp16(sdst + off, (const char*)gsrc + off);
}
#define CP_COMMIT() asm volatile("cp.async.commit_group;")
#define CP_WAIT(n)  asm volatile("cp.async.wait_group %0;" :: "n"(n))

__device__ __forceinline__ void ldsm4(uint32_t a, uint32_t r[4]) {
    asm volatile("ldmatrix.sync.aligned.m8n8.x4.shared.b16 {%0,%1,%2,%3}, [%4];"
        : "=r"(r[0]), "=r"(r[1]), "=r"(r[2]), "=r"(r[3]) : "r"(a));
}
__device__ __forceinline__ void ldsm4t(uint32_t a, uint32_t r[4]) {
    asm volatile("ldmatrix.sync.aligned.m8n8.x4.trans.shared.b16 {%0,%1,%2,%3}, [%4];"
        : "=r"(r[0]), "=r"(r[1]), "=r"(r[2]), "=r"(r[3]) : "r"(a));
}
__device__ __forceinline__ void mma(float c[4], const uint32_t a[4], uint32_t b0, uint32_t b1) {
    asm volatile("mma.sync.aligned.m16n8k16.row.col.f32.bf16.bf16.f32 "
        "{%0,%1,%2,%3},{%4,%5,%6,%7},{%8,%9},{%0,%1,%2,%3};"
        : "+f"(c[0]), "+f"(c[1]), "+f"(c[2]), "+f"(c[3])
        : "r"(a[0]), "r"(a[1]), "r"(a[2]), "r"(a[3]), "r"(b0), "r"(b1));
}
__device__ __forceinline__ uint32_t ldsma(uint32_t base, int row0, int cs0, int stride, int lane) {
    int r = row0 + (lane & 15);
    return base + (uint32_t)(r * stride) + ((uint32_t)((cs0 + (lane >> 4)) ^ (r & 7)) << 4);
}

// ===================== prep kernel =====================
__global__ void prep_kernel(const float* __restrict__ states, const float* __restrict__ action,
                            const float* __restrict__ We, const float* __restrict__ Wn)
{
    int tid = blockIdx.x * blockDim.x + threadIdx.x;
    int NT  = gridDim.x * blockDim.x;
    for (int p = tid; p < KN * 8192 * 32; p += NT) {
        int d2 = p & 31, b = (p >> 5) & 8191, j = p >> 18;
        float2 v = *(const float2*)&states[((size_t)b * KN + j) * 64 + 2 * d2];
        uint32_t h2, l2; split2(v.x, v.y, h2, l2);
        uint32_t off = ((uint32_t)(j * 8192 + b) << 7)
                     + ((uint32_t)(((d2 >> 2) ^ (b & 7))) << 4) + ((uint32_t)(d2 & 3) << 2);
        *(uint32_t*)(g_sHi + off) = h2;
        *(uint32_t*)(g_sLo + off) = l2;
    }
    for (int p = tid; p < KN * 8192 * 8; p += NT) {
        int a2 = p & 7, b = (p >> 3) & 8191, j = p >> 16;
        float2 v = *(const float2*)&action[((size_t)b * KN + j) * 16 + 2 * a2];
        uint32_t h2, l2; split2(v.x, v.y, h2, l2);
        uint32_t off = ((uint32_t)(j * 8192 + b) << 5) + ((uint32_t)a2 << 2);
        *(uint32_t*)(g_aHi + off) = h2;
        *(uint32_t*)(g_aLo + off) = l2;
    }
    for (int p = tid; p < 90 * 128 * 64; p += NT) {
        int h2i = p & 63, k = (p >> 6) & 127, e = p >> 13;
        float2 v = *(const float2*)&We[((size_t)e * 128 + k) * 128 + 2 * h2i];
        uint32_t h2, l2; split2(v.x, v.y, h2, l2);
        uint32_t off = ((uint32_t)(e * 128 + k) << 8)
                     + ((uint32_t)(((h2i >> 2) ^ (k & 7))) << 4) + ((uint32_t)(h2i & 3) << 2);
        *(uint32_t*)(g_WeHi + off) = h2;
        *(uint32_t*)(g_WeLo + off) = l2;
    }
    for (int p = tid; p < KN * 208 * 32; p += NT) {
        int d2 = p & 31, fi = p >> 5;
        int f = fi % 208, i = fi / 208;
        float2 v = *(const float2*)&Wn[((size_t)i * 208 + f) * 64 + 2 * d2];
        uint32_t h2, l2; split2(v.x, v.y, h2, l2);
        uint32_t off = ((uint32_t)(i * 208 + f) << 7)
                     + ((uint32_t)(((d2 >> 2) ^ (f & 7))) << 4) + ((uint32_t)(d2 & 3) << 2);
        *(uint32_t*)(g_WnHi + off) = h2;
        *(uint32_t*)(g_WnLo + off) = l2;
    }
}

// ===================== main kernel =====================
extern "C" __global__ void __launch_bounds__(256, 1)
gnn_hmma_kernel(const float* __restrict__ b_edge,   // [E,H]
                const float* __restrict__ b_node,   // [K,D]
                float* __restrict__ out)            // [B,K,D]
{
    extern __shared__ char smem[];
    const uint32_t sb = (uint32_t)__cvta_generic_to_shared(smem);

    const int i    = blockIdx.y;
    const int b0   = blockIdx.x * TB;
    const int tid  = threadIdx.x;
    const int lane = tid & 31;
    const int wid  = tid >> 5;
    const int wm   = wid & 3;    // 4 m-warps: rows 32*wm .. +31
    const int wn   = wid >> 2;   // 2 n-warps: edge cols 64*wn, node cols 32*wn
    const int m0   = 32 * wm;

    // ---- prologue ----
    cpblk(sb + SI_HI,  g_sHi + (size_t)(i * 8192 + b0) * 128, 16384, tid);
    cpblk(sb + SI_LO,  g_sLo + (size_t)(i * 8192 + b0) * 128, 16384, tid);
    cpblk(sb + ACT_HI, g_aHi + (size_t)(i * 8192 + b0) * 32,  4096, tid);
    cpblk(sb + ACT_LO, g_aLo + (size_t)(i * 8192 + b0) * 32,  4096, tid);
    {
        int j0 = (i == 0) ? 1 : 0;
        cpblk(sb + SJ_HI, g_sHi + (size_t)(j0 * 8192 + b0) * 128, 16384, tid);
        cpblk(sb + SJ_LO, g_sLo + (size_t)(j0 * 8192 + b0) * 128, 16384, tid);
        cpblk(sb + W0,          g_WeHi + (size_t)(i * 9) * 32768, 32768, tid);
        cpblk(sb + W0 + 32768,  g_WeLo + (size_t)(i * 9) * 32768, 32768, tid);
        cpblk(sb + BIASALL, b_edge + (size_t)(i * 9) * 128, 4608, tid);
    }
    CP_COMMIT();                                             // g0
    cpblk(sb + W0 + 65536,          g_WeHi + (size_t)(i * 9 + 1) * 32768, 32768, tid);
    cpblk(sb + W0 + 65536 + 32768,  g_WeLo + (size_t)(i * 9 + 1) * 32768, 32768, tid);
    CP_COMMIT();                                             // g1 (W1)

    float C[64], agg2[64];
    #pragma unroll
    for (int q = 0; q < 64; ++q) agg2[q] = 0.0f;

    // ---- edge loop ----
    #pragma unroll
    for (int t = 0; t < 9; ++t) {
        if (t == 0) { CP_WAIT(1); } else { CP_WAIT(2); }     // W_t + (t==0: sj0/bias) ready
        __syncthreads();

        // init C from bias
        {
            const float* bs = (const float*)(smem + BIASALL) + t * 128;
            #pragma unroll
            for (int m = 0; m < 2; ++m)
                #pragma unroll
                for (int p = 0; p < 4; ++p)
                    #pragma unroll
                    for (int co = 0; co < 2; ++co) {
                        int h = 64 * wn + p * 16 + co * 8 + (lane & 3) * 2;
                        float* c = C + m * 32 + p * 8 + co * 4;
                        c[0] = bs[h]; c[1] = bs[h + 1];
                        c[2] = bs[h]; c[3] = bs[h + 1];
                    }
        }

        const uint32_t wHi = sb + W0 + (uint32_t)(t & 1) * 65536u;
        const uint32_t wLo = wHi + 32768u;

        #pragma unroll
        for (int kk = 0; kk < 8; ++kk) {
            if (kk == 4) { CP_WAIT(1); __syncthreads(); }    // sj_t ready (t>=1); no-op t==0
            const uint32_t aHiB = (kk < 4) ? (sb + SI_HI) : (sb + SJ_HI);
            const uint32_t aLoB = (kk < 4) ? (sb + SI_LO) : (sb + SJ_LO);
            const int kl = kk & 3;
            uint32_t ah[2][4], al[2][4];
            ldsm4(ldsma(aHiB, m0,      2 * kl, 128, lane), ah[0]);
            ldsm4(ldsma(aHiB, m0 + 16, 2 * kl, 128, lane), ah[1]);
            ldsm4(ldsma(aLoB, m0,      2 * kl, 128, lane), al[0]);
            ldsm4(ldsma(aLoB, m0 + 16, 2 * kl, 128, lane), al[1]);
            const int krow = 16 * kk;
            uint32_t bh[4][4], bl[4][4];
            #pragma unroll
            for (int p = 0; p < 4; ++p) {
                ldsm4t(ldsma(wHi, krow, 8 * wn + 2 * p, 256, lane), bh[p]);
                ldsm4t(ldsma(wLo, krow, 8 * wn + 2 * p, 256, lane), bl[p]);
            }
            // pass hh (16 independent accumulators)
            #pragma unroll
            for (int m = 0; m < 2; ++m)
                #pragma unroll
                for (int p = 0; p < 4; ++p) {
                    mma(C + m * 32 + p * 8,     ah[m], bh[p][0], bh[p][1]);
                    mma(C + m * 32 + p * 8 + 4, ah[m], bh[p][2], bh[p][3]);
                }
            // pass hl
            #pragma unroll
            for (int m = 0; m < 2; ++m)
                #pragma unroll
                for (int p = 0; p < 4; ++p) {
                    mma(C + m * 32 + p * 8,     ah[m], bl[p][0], bl[p][1]);
                    mma(C + m * 32 + p * 8 + 4, ah[m], bl[p][2], bl[p][3]);
                }
            // pass lh
            #pragma unroll
            for (int m = 0; m < 2; ++m)
                #pragma unroll
                for (int p = 0; p < 4; ++p) {
                    mma(C + m * 32 + p * 8,     al[m], bh[p][0], bh[p][1]);
                    mma(C + m * 32 + p * 8 + 4, al[m], bh[p][2], bh[p][3]);
                }
        }
        __syncthreads();   // sj_t + W_t fully consumed

        // prefetch: sj_{t+1} (own group), then W_{t+2} or W_node
        if (t < 8) {
            int jn = (t + 1) + ((t + 1) >= i ? 1 : 0);
            cpblk(sb + SJ_HI, g_sHi + (size_t)(jn * 8192 + b0) * 128, 16384, tid);
            cpblk(sb + SJ_LO, g_sLo + (size_t)(jn * 8192 + b0) * 128, 16384, tid);
            CP_COMMIT();                                     // gA: sj_{t+1}
            if (t < 7) {
                uint32_t wb = sb + W0 + (uint32_t)(t & 1) * 65536u;
                cpblk(wb,          g_WeHi + (size_t)(i * 9 + t + 2) * 32768, 32768, tid);
                cpblk(wb + 32768,  g_WeLo + (size_t)(i * 9 + t + 2) * 32768, 32768, tid);
            } else {
                cpblk(sb + WN_HI, g_WnHi + (size_t)i * 26624, 26624, tid);
                cpblk(sb + WN_LO, g_WnLo + (size_t)i * 26624, 26624, tid);
            }
            CP_COMMIT();                                     // gB: W_{t+2} / WN
        }

        // epilogue (MUFU overlaps in-flight cp.async + other warps' MMAs)
        #pragma unroll
        for (int q = 0; q < 64; ++q) agg2[q] += tanha(C[q]);
    }

    // ---- node phase: write agg as bf16 hi/lo A-tile [128r][128k] (aliases W buf 0) ----
    #pragma unroll
    for (int m = 0; m < 2; ++m)
        #pragma unroll
        for (int p = 0; p < 4; ++p)
            #pragma unroll
            for (int co = 0; co < 2; ++co) {
                int h = 64 * wn + p * 16 + co * 8 + (lane & 3) * 2;
                int idx = m * 32 + p * 8 + co * 4;
                #pragma unroll
                for (int hh = 0; hh < 2; ++hh) {
                    int r = m0 + m * 16 + (lane >> 2) + 8 * hh;
                    uint32_t h2, l2;
                    split2(agg2[idx + 2 * hh], agg2[idx + 2 * hh + 1], h2, l2);
                    uint32_t off = (uint32_t)(r * 256)
                                 + ((uint32_t)(((h >> 3) ^ (r & 7))) << 4)
                                 + ((uint32_t)(h & 7) << 1);
                    *(uint32_t*)(smem + AGG_HI + off) = h2;
                    *(uint32_t*)(smem + AGG_LO + off) = l2;
                }
            }
    CP_WAIT(0);          // W_node staged
    __syncthreads();

    // init C2 from node bias
    float C2[32];
    #pragma unroll
    for (int m = 0; m < 2; ++m)
        #pragma unroll
        for (int p4 = 0; p4 < 4; ++p4) {
            int d = 32 * wn + p4 * 8 + (lane & 3) * 2;
            float2 bn = *(const float2*)&b_node[(size_t)i * 64 + d];
            float* c = C2 + m * 16 + p4 * 4;
            c[0] = bn.x; c[1] = bn.y; c[2] = bn.x; c[3] = bn.y;
        }

    // node GEMM: 13 ks-steps of k16 over F=208
    #pragma unroll
    for (int ks = 0; ks < 13; ++ks) {
        uint32_t ah[2][4], al[2][4];
        if (ks < 4) {
            ldsm4(ldsma(sb + SI_HI, m0,      2 * ks, 128, lane), ah[0]);
            ldsm4(ldsma(sb + SI_HI, m0 + 16, 2 * ks, 128, lane), ah[1]);
            ldsm4(ldsma(sb + SI_LO, m0,      2 * ks, 128, lane), al[0]);
            ldsm4(ldsma(sb + SI_LO, m0 + 16, 2 * ks, 128, lane), al[1]);
        } else if (ks == 4) {
            #pragma unroll
            for (int m = 0; m < 2; ++m) {
                int r = m0 + m * 16 + (lane & 15);
                uint32_t ao = (uint32_t)(r * 32) + ((uint32_t)(lane >> 4) << 4);
                ldsm4(sb + ACT_HI + ao, ah[m]);
                ldsm4(sb + ACT_LO + ao, al[m]);
            }
        } else {
            ldsm4(ldsma(sb + AGG_HI, m0,      2 * (ks - 5), 256, lane), ah[0]);
            ldsm4(ldsma(sb + AGG_HI, m0 + 16, 2 * (ks - 5), 256, lane), ah[1]);
            ldsm4(ldsma(sb + AGG_LO, m0,      2 * (ks - 5), 256, lane), al[0]);
            ldsm4(ldsma(sb + AGG_LO, m0 + 16, 2 * (ks - 5), 256, lane), al[1]);
        }
        #pragma unroll
        for (int p = 0; p < 2; ++p) {
            uint32_t bh[4], bl[4];
            ldsm4t(ldsma(sb + WN_HI, 16 * ks, 4 * wn + 2 * p, 128, lane), bh);
            ldsm4t(ldsma(sb + WN_LO, 16 * ks, 4 * wn + 2 * p, 128, lane), bl);
            #pragma unroll
            for (int m = 0; m < 2; ++m) {
                float* c0 = C2 + m * 16 + (2 * p) * 4;
                float* c1 = C2 + m * 16 + (2 * p + 1) * 4;
                mma(c0, ah[m], bh[0], bh[1]); mma(c1, ah[m], bh[2], bh[3]);
                mma(c0, ah[m], bl[0], bl[1]); mma(c1, ah[m], bl[2], bl[3]);
                mma(c0, al[m], bh[0], bh[1]); mma(c1, al[m], bh[2], bh[3]);
            }
        }
    }

    // ---- final epilogue: tanh + store ----
    #pragma unroll
    for (int m = 0; m < 2; ++m)
        #pragma unroll
        for (int p4 = 0; p4 < 4; ++p4) {
            int d = 32 * wn + p4 * 8 + (lane & 3) * 2;
            int r0 = m0 + m * 16 + (lane >> 2);
            const float* c = C2 + m * 16 + p4 * 4;
            float2 v0 = { tanha(c[0]), tanha(c[1]) };
            float2 v1 = { tanha(c[2]), tanha(c[3]) };
            *(float2*)&out[((size_t)(b0 + r0)     * KN + i) * 64 + d] = v0;
            *(float2*)&out[((size_t)(b0 + r0 + 8) * KN + i) * 64 + d] = v1;
        }
}

extern "C" void kernel_launch(void* const* d_in, const int* in_sizes, int n_in,
                              void* d_out, int out_size)
{
    const float* states = (const float*)d_in[0];
    const float* action = (const float*)d_in[1];
    const float* W_edge = (const float*)d_in[2];
    const float* b_edge = (const float*)d_in[3];
    const float* W_node = (const float*)d_in[4];
    const float* b_node = (const float*)d_in[5];
    float* out = (float*)d_out;

    int B = in_sizes[0] / (KN * 64);   // 8192

    prep_kernel<<<2048, 256>>>(states, action, W_edge, W_node);

    cudaFuncSetAttribute(gnn_hmma_kernel,
                         cudaFuncAttributeMaxDynamicSharedMemorySize, SMEM_TOTAL);
    dim3 grid(B / TB, KN);
    gnn_hmma_kernel<<<grid, 256, SMEM_TOTAL>>>(b_edge, b_node, out);
}